// round 1
// baseline (speedup 1.0000x reference)
#include <cuda_runtime.h>

#define DIM 4096
#define NQ 12
#define DEPTH 4

// SMEM swizzle: xor bits [2:4] with bits [9:11]. Involution (bits 9-11 untouched),
// keeps float4 alignment (bits 0-1 untouched), makes pass-B strided access
// bank-conflict-free.
__device__ __forceinline__ int ss(int i) { return i ^ (((i >> 9) & 7) << 2); }

// Composed CNOT-ring permutation: s'[i] = s[sigma(i)].
// Gates applied in order q=0..11: CNOT(control=q, target=(q+1)%12).
// Gather index composes innermost-first => apply sigma_q for q = 11 .. 0.
// Qubit q lives at index bit (11-q).
__device__ __forceinline__ int sigma(int i) {
    int j = i;
#pragma unroll
    for (int q = NQ - 1; q >= 0; --q) {
        const int cpos = NQ - 1 - q;
        const int t = (q + 1) % NQ;
        const int tpos = NQ - 1 - t;
        j ^= ((j >> cpos) & 1) << tpos;
    }
    return j;
}

__global__ __launch_bounds__(1024, 1)
void qsim_kernel(const float* __restrict__ x, const float* __restrict__ theta,
                 const float* __restrict__ w, const float* __restrict__ b,
                 float* __restrict__ out) {
    __shared__ float S[DIM];
    __shared__ float CS[DEPTH * NQ];
    __shared__ float SN[DEPTH * NQ];
    __shared__ float red[64];

    const int tid = threadIdx.x;
    const int lane = tid & 31;
    const int wid = tid >> 5;

    // Precompute cos/sin of half-angles: angle[d][q] = theta[d][q] + 0.1*x[q]
    if (tid < DEPTH * NQ) {
        const int q = tid % NQ;
        const float a = 0.5f * (theta[tid] + 0.1f * x[q]);
        CS[tid] = cosf(a);
        SN[tid] = sinf(a);
    }
    __syncthreads();

    // Pass-A layout: i = (wid<<7) | (lane<<2) | k   (k = 0..3 local)
    //   bits 0-1 local, bits 2-6 lane, bits 7-11 warp
    const int baseA = (wid << 7) | (lane << 2);
    // Pass-B layout: i = ((lane>>2)<<9) | (k<<7) | (wid<<2) | (lane&3)
    //   bits 7-8 local, bits 9-11 lane(bits 2-4), bits 0-1 lane(bits 0-1), bits 2-6 warp
    const int baseB = ((lane >> 2) << 9) | (wid << 2) | (lane & 3);

    float v[4];

    for (int d = 0; d < DEPTH; ++d) {
        const float* Cd = CS + d * NQ;
        const float* Sd = SN + d * NQ;

        // ================= Pass A: rotate bits 0..6 (qubits 11..5) ============
        if (d == 0) {
            // state = e0, no SMEM round-trip needed
            v[0] = v[1] = v[2] = v[3] = 0.f;
            if (baseA == 0) v[0] = 1.f;
        } else {
            // fuse previous layer's CNOT ring into the gather
#pragma unroll
            for (int k = 0; k < 4; ++k) v[k] = S[ss(sigma(baseA | k))];
        }

        // bit0 -> qubit 11 : pairs (v0,v1),(v2,v3)
        {
            const float c = Cd[11], s = Sd[11];
            float n0 = c * v[0] - s * v[1], n1 = s * v[0] + c * v[1];
            float n2 = c * v[2] - s * v[3], n3 = s * v[2] + c * v[3];
            v[0] = n0; v[1] = n1; v[2] = n2; v[3] = n3;
        }
        // bit1 -> qubit 10 : pairs (v0,v2),(v1,v3)
        {
            const float c = Cd[10], s = Sd[10];
            float n0 = c * v[0] - s * v[2], n2 = s * v[0] + c * v[2];
            float n1 = c * v[1] - s * v[3], n3 = s * v[1] + c * v[3];
            v[0] = n0; v[2] = n2; v[1] = n1; v[3] = n3;
        }
        // lane bits 0..4 == index bits 2..6 -> qubits 9..5
#pragma unroll
        for (int bb = 0; bb < 5; ++bb) {
            const int m = 1 << bb;
            const float c = Cd[9 - bb], s = Sd[9 - bb];
            const float se = (lane & m) ? s : -s;
#pragma unroll
            for (int k = 0; k < 4; ++k) {
                const float o = __shfl_xor_sync(0xffffffffu, v[k], m);
                v[k] = c * v[k] + se * o;
            }
        }
#pragma unroll
        for (int k = 0; k < 4; ++k) S[ss(baseA | k)] = v[k];
        __syncthreads();

        // ================= Pass B: rotate bits 7..11 (qubits 4..0) ============
#pragma unroll
        for (int k = 0; k < 4; ++k) v[k] = S[ss(baseB | (k << 7))];

        // bit7 -> qubit 4 : pairs (v0,v1),(v2,v3)
        {
            const float c = Cd[4], s = Sd[4];
            float n0 = c * v[0] - s * v[1], n1 = s * v[0] + c * v[1];
            float n2 = c * v[2] - s * v[3], n3 = s * v[2] + c * v[3];
            v[0] = n0; v[1] = n1; v[2] = n2; v[3] = n3;
        }
        // bit8 -> qubit 3 : pairs (v0,v2),(v1,v3)
        {
            const float c = Cd[3], s = Sd[3];
            float n0 = c * v[0] - s * v[2], n2 = s * v[0] + c * v[2];
            float n1 = c * v[1] - s * v[3], n3 = s * v[1] + c * v[3];
            v[0] = n0; v[2] = n2; v[1] = n1; v[3] = n3;
        }
        // lane bits 2..4 == index bits 9..11 -> qubits 2..0
#pragma unroll
        for (int bb = 0; bb < 3; ++bb) {
            const int m = 4 << bb;
            const float c = Cd[2 - bb], s = Sd[2 - bb];
            const float se = (lane & m) ? s : -s;
#pragma unroll
            for (int k = 0; k < 4; ++k) {
                const float o = __shfl_xor_sync(0xffffffffu, v[k], m);
                v[k] = c * v[k] + se * o;
            }
        }
#pragma unroll
        for (int k = 0; k < 4; ++k) S[ss(baseB | (k << 7))] = v[k];
        __syncthreads();
    }

    // ============ Readout (final CNOT ring fused into gather) ============
    float a0 = 0.f, a1 = 0.f;
#pragma unroll
    for (int k = 0; k < 4; ++k) {
        const int i = baseA | k;
        const float vv = S[ss(sigma(i))];
        out[2 + i] = vv;              // final state
        const float p = vv * vv;      // |amp|^2
        a0 += p * w[i];
        a1 += p * w[DIM + i];
    }
#pragma unroll
    for (int o = 16; o > 0; o >>= 1) {
        a0 += __shfl_down_sync(0xffffffffu, a0, o);
        a1 += __shfl_down_sync(0xffffffffu, a1, o);
    }
    if (lane == 0) { red[wid] = a0; red[32 + wid] = a1; }
    __syncthreads();
    if (wid == 0) {
        float r0 = red[lane], r1 = red[32 + lane];
#pragma unroll
        for (int o = 16; o > 0; o >>= 1) {
            r0 += __shfl_down_sync(0xffffffffu, r0, o);
            r1 += __shfl_down_sync(0xffffffffu, r1, o);
        }
        if (lane == 0) {
            out[0] = r0 + b[0];
            out[1] = r1 + b[1];
        }
    }
}

extern "C" void kernel_launch(void* const* d_in, const int* in_sizes, int n_in,
                              void* d_out, int out_size) {
    // Identify inputs by element count (setup_inputs order: x, theta, w_out, b_out)
    const float* x = nullptr;
    const float* th = nullptr;
    const float* w = nullptr;
    const float* b = nullptr;
    for (int i = 0; i < n_in; ++i) {
        const int s = in_sizes[i];
        if (s == NQ) x = (const float*)d_in[i];
        else if (s == DEPTH * NQ) th = (const float*)d_in[i];
        else if (s == 2 * DIM) w = (const float*)d_in[i];
        else if (s == 2) b = (const float*)d_in[i];
    }
    qsim_kernel<<<1, 1024>>>(x, th, w, b, (float*)d_out);
}

// round 2
// speedup vs baseline: 1.4244x; 1.4244x over previous
#include <cuda_runtime.h>

#define DIM 4096
#define NQ 12
#define DEPTH 4

// ---- GF(2)-linear helpers (all fold to constants for literal args) ----

// Composed CNOT-ring permutation (gather form): out_i = x_i ^ x_{i+1} for i=0..9,
// out10 = x10^x11^x0, out11 = x11^x0.  Derived from sequential c=1..11 sweep
// after j ^= bit0<<11; verified against the iterative reference form.
__host__ __device__ __forceinline__ constexpr int sig(int x) {
    int r = (x ^ (x >> 1)) & 0x3FF;
    r |= (((x >> 10) ^ (x >> 11) ^ x) & 1) << 10;
    r |= (((x >> 11) ^ x) & 1) << 11;
    return r;
}
// Placement P (used for inter-layer state: B-store / A-load-with-sigma / init / readout)
// bank bits: b0^=y5, b1^=y7, b2^=y6  -> both access patterns full-rank (conflict-free)
__host__ __device__ __forceinline__ constexpr int pp(int y) {
    return y ^ ((y >> 5) & 1) ^ (((y >> 7) & 1) << 1) ^ (((y >> 6) & 1) << 2);
}
// Placement Q (intra-layer: A-store / B-load)
// bank bits: b0^=y8^y6, b1^=y7, b2^=y5, b3^=y6 -> both patterns full-rank
__host__ __device__ __forceinline__ constexpr int qq(int y) {
    return y ^ (((y >> 8) ^ (y >> 6)) & 1) ^ (((y >> 7) & 1) << 1)
             ^ (((y >> 5) & 1) << 2) ^ (((y >> 6) & 1) << 3);
}
// Layout-B k-bit embedding: k0..k2 -> index bits 9..11, k3 -> bit 8
__host__ __device__ __forceinline__ constexpr int kbB(int k) {
    return ((k & 7) << 9) | (((k >> 3) & 1) << 8);
}

__global__ __launch_bounds__(256, 1)
void qsim_kernel(const float* __restrict__ x, const float* __restrict__ theta,
                 const float* __restrict__ w, const float* __restrict__ b,
                 float* __restrict__ out) {
    __shared__ float S0[DIM];   // inter-layer buffer (pp placement)
    __shared__ float S1[DIM];   // intra-layer buffer (qq placement)
    __shared__ float CS[DEPTH * NQ];
    __shared__ float SN[DEPTH * NQ];
    __shared__ float red[16];

    const int tid = threadIdx.x;
    const int lane = tid & 31;
    const int wid = tid >> 5;

    // half-angle cos/sin: angle[d][q] = theta[d][q] + 0.1*x[q]
    if (tid < DEPTH * NQ) {
        const int q = tid % NQ;
        const float a = 0.5f * (theta[tid] + 0.1f * x[q]);
        float s, c;
        __sincosf(a, &s, &c);
        CS[tid] = c;
        SN[tid] = s;
    }
    __syncthreads();

    // Layout A: i = w<<9 | lane<<4 | k      (k bits0-3, lane bits4-8, w bits9-11)
    // Layout B: i = kbB(k) | lane<<3 | w    (w bits0-2, lane bits3-7, k bits8-11)
    const int baseA = (wid << 9) | (lane << 4);
    const int baseB = (lane << 3) | wid;
    const int ldA = pp(sig(baseA));  // ^ pp(sig(k))        [A gather, prev ring fused]
    const int stA = qq(baseA);       // ^ k  (qq(k)==k here) [A scatter]
    const int ldB = qq(baseB);       // ^ qq(kbB(k))         [B gather]
    const int stB = pp(baseB);       // ^ kbB(k)             [B scatter]

    float v[16];

    // ================= Layer 0: product state (all 12 RYs on e0) ============
    {
        const float* C = CS;
        const float* Sn = SN;
        float P = 1.f;
#pragma unroll
        for (int bp = 0; bp < 8; ++bp) {
            const int bit = (baseB >> bp) & 1;
            P *= bit ? Sn[11 - bp] : C[11 - bp];   // index bit bp -> qubit 11-bp
        }
        // k0->q2, k1->q1, k2->q0, k3->q3
        float a01[4], a23[4];
#pragma unroll
        for (int t = 0; t < 4; ++t) {
            a01[t] = ((t & 1) ? Sn[2] : C[2]) * ((t & 2) ? Sn[1] : C[1]);
            a23[t] = ((t & 1) ? Sn[0] : C[0]) * ((t & 2) ? Sn[3] : C[3]);
        }
#pragma unroll
        for (int k = 0; k < 16; ++k)
            S0[stB ^ kbB(k)] = P * a01[k & 3] * a23[k >> 2];
    }
    __syncthreads();

    // ================= Layers 1..3 ================
    for (int d = 1; d < DEPTH; ++d) {
        const float* C = CS + d * NQ;
        const float* Sn = SN + d * NQ;

        // ---- Pass A: gather (prev CNOT ring fused), rotate qubits 11..8 (reg)
        //      and 7..3 (shfl), scatter to S1
#pragma unroll
        for (int k = 0; k < 16; ++k) v[k] = S0[ldA ^ pp(sig(k))];

#pragma unroll
        for (int rb = 0; rb < 4; ++rb) {           // index bit rb -> qubit 11-rb
            const int m = 1 << rb;
            const float c = C[11 - rb], s = Sn[11 - rb];
            float nv[16];
#pragma unroll
            for (int k = 0; k < 16; ++k)
                nv[k] = c * v[k] + ((k & m) ? s : -s) * v[k ^ m];
#pragma unroll
            for (int k = 0; k < 16; ++k) v[k] = nv[k];
        }
#pragma unroll
        for (int bs = 0; bs < 5; ++bs) {           // lane bit bs -> qubit 7-bs
            const int m = 1 << bs;
            const float c = C[7 - bs], s = Sn[7 - bs];
            const float se = (lane & m) ? s : -s;
#pragma unroll
            for (int k = 0; k < 16; ++k) {
                const float o = __shfl_xor_sync(0xffffffffu, v[k], m);
                v[k] = c * v[k] + se * o;
            }
        }
#pragma unroll
        for (int k = 0; k < 16; ++k) S1[stA ^ k] = v[k];
        __syncthreads();

        // ---- Pass B: gather from S1, rotate qubits 2,1,0 (all in-register),
        //      scatter to S0 (inter-layer placement)
#pragma unroll
        for (int k = 0; k < 16; ++k) v[k] = S1[ldB ^ qq(kbB(k))];

#pragma unroll
        for (int rb = 0; rb < 3; ++rb) {           // k bit rb -> index bit 9+rb -> qubit 2-rb
            const int m = 1 << rb;
            const float c = C[2 - rb], s = Sn[2 - rb];
            float nv[16];
#pragma unroll
            for (int k = 0; k < 16; ++k)
                nv[k] = c * v[k] + ((k & m) ? s : -s) * v[k ^ m];
#pragma unroll
            for (int k = 0; k < 16; ++k) v[k] = nv[k];
        }
#pragma unroll
        for (int k = 0; k < 16; ++k) S0[stB ^ kbB(k)] = v[k];
        __syncthreads();
    }

    // ================= Readout (final CNOT ring fused) ================
    // Readout layout: r = w<<9 | k<<5 | lane  (coalesced global stores/loads)
    const int baseR = (wid << 9) | lane;
    const int ldR = pp(sig(baseR));
    float a0 = 0.f, a1 = 0.f;
#pragma unroll
    for (int k = 0; k < 16; ++k) {
        const int r = baseR | (k << 5);
        const float vv = S0[ldR ^ pp(sig(k << 5))];
        out[2 + r] = vv;
        const float p = vv * vv;
        a0 += p * w[r];
        a1 += p * w[DIM + r];
    }
#pragma unroll
    for (int o = 16; o > 0; o >>= 1) {
        a0 += __shfl_down_sync(0xffffffffu, a0, o);
        a1 += __shfl_down_sync(0xffffffffu, a1, o);
    }
    if (lane == 0) { red[wid] = a0; red[8 + wid] = a1; }
    __syncthreads();
    if (wid == 0) {
        float r0 = (lane < 8) ? red[lane] : 0.f;
        float r1 = (lane < 8) ? red[8 + lane] : 0.f;
#pragma unroll
        for (int o = 4; o > 0; o >>= 1) {
            r0 += __shfl_down_sync(0xffffffffu, r0, o);
            r1 += __shfl_down_sync(0xffffffffu, r1, o);
        }
        if (lane == 0) {
            out[0] = r0 + b[0];
            out[1] = r1 + b[1];
        }
    }
}

extern "C" void kernel_launch(void* const* d_in, const int* in_sizes, int n_in,
                              void* d_out, int out_size) {
    const float* x = nullptr;
    const float* th = nullptr;
    const float* w = nullptr;
    const float* b = nullptr;
    for (int i = 0; i < n_in; ++i) {
        const int s = in_sizes[i];
        if (s == NQ) x = (const float*)d_in[i];
        else if (s == DEPTH * NQ) th = (const float*)d_in[i];
        else if (s == 2 * DIM) w = (const float*)d_in[i];
        else if (s == 2) b = (const float*)d_in[i];
    }
    qsim_kernel<<<1, 256>>>(x, th, w, b, (float*)d_out);
}